// round 12
// baseline (speedup 1.0000x reference)
#include <cuda_runtime.h>
#include <stdint.h>
#include <math.h>

// Problem constants (fixed by setup_inputs)
#define B_   4
#define N_   8192
#define M_   8192
#define KNN  16
#define C_   64
#define NBLK1 512
#define MK_INV (1.0f/((float)M_*(float)KNN))
#define FS4  257   // padded feat row stride in float4 / ulonglong2 units (1028 floats)
#define PTS_ 32    // points per k4 block

typedef unsigned long long ull;

// ---------------- packed f32x2 helpers (Blackwell base ISA) ----------------
__device__ __forceinline__ ull fma2(ull a, ull b, ull c) {
    ull d;
    asm("fma.rn.f32x2 %0, %1, %2, %3;" : "=l"(d) : "l"(a), "l"(b), "l"(c));
    return d;
}
__device__ __forceinline__ ull dup2(float x) {
    ull r;
    asm("mov.b64 %0, {%1, %2};" : "=l"(r) : "f"(x), "f"(x));
    return r;
}
__device__ __forceinline__ float2 unpack2(ull v) {
    float2 f;
    asm("mov.b64 {%0, %1}, %2;" : "=f"(f.x), "=f"(f.y) : "l"(v));
    return f;
}

// Partition-reduce 32 values across 32 lanes: 31 shfl total.
// On return, lane l holds the full sum of value index l.
__device__ __forceinline__ float preduce32(float* v, int lane) {
    #pragma unroll
    for (int m = 16; m >= 1; m >>= 1) {
        bool b = (lane & m) != 0;
        #pragma unroll
        for (int i = 0; i < m; i++) {
            float send = b ? v[i] : v[i + m];
            float r = __shfl_xor_sync(0xffffffffu, send, m);
            v[i] = (b ? v[i + m] : v[i]) + r;
        }
    }
    return v[0];
}

// Max over 16-lane half-warp group via one REDUX (valid for values >= 0:
// non-negative IEEE fp32 bit patterns are monotone as u32).
__device__ __forceinline__ float redux_max16(float v, int lane) {
    unsigned mask = (lane & 16) ? 0xFFFF0000u : 0x0000FFFFu;
    unsigned r;
    asm("redux.sync.max.u32 %0, %1, %2;" : "=r"(r) : "r"(__float_as_uint(v)), "r"(mask));
    return __uint_as_float(r);
}

// ---------------- device scratch ----------------
__device__ float  g_xt  [B_*N_*C_];        // x transposed: [B][N][64]
__device__ float  g_post[B_*N_*4];         // pos transposed+padded
__device__ float4 g_pts [B_*M_*KNN];       // normalized pts per neighbor
__device__ float  g_dw  [B_*M_*KNN];       // distance weights
__device__ float  g_t2  [(size_t)B_*M_*256]; // fc2 out, layout [b][m][k][j]
__device__ float  g_part1[B_*NBLK1*16];
__device__ float  g_part2[B_*NBLK1*32];
__device__ float2 g_ab1[B_*16];
__device__ float2 g_ab2[B_*16];
__device__ __align__(16) float g_cvP[64*1024];  // cv repacked [o][d], d=j*64+c

// ---------------- prep kernels ----------------
__global__ void k_xt(const float* __restrict__ x) {
    __shared__ float tile[32][33];
    int b  = blockIdx.z;
    int c0 = blockIdx.y * 32;
    int n0 = blockIdx.x * 32;
    int tx = threadIdx.x, ty = threadIdx.y;   // 32 x 8
    #pragma unroll
    for (int i = 0; i < 32; i += 8)
        tile[ty + i][tx] = x[(size_t)(b*C_ + c0 + ty + i)*N_ + n0 + tx];
    __syncthreads();
    #pragma unroll
    for (int i = 0; i < 32; i += 8)
        g_xt[(size_t)(b*N_ + n0 + ty + i)*C_ + c0 + tx] = tile[tx][ty + i];
}

__global__ void k_pos(const float* __restrict__ pos) {
    int b = blockIdx.y;
    int n = blockIdx.x * 256 + threadIdx.x;
    float4 v;
    v.x = pos[(size_t)(b*3 + 0)*N_ + n];
    v.y = pos[(size_t)(b*3 + 1)*N_ + n];
    v.z = pos[(size_t)(b*3 + 2)*N_ + n];
    v.w = 0.0f;
    ((float4*)g_post)[b*N_ + n] = v;
}

// cv2[o][d] with d = j*64 + c
__global__ void k_cvp(const float* __restrict__ cv) {
    int g = blockIdx.x * 256 + threadIdx.x;  // 65536
    int o = g >> 10;
    int d = g & 1023;
    int c = d & 63;
    int j = d >> 6;
    g_cvP[g] = cv[(size_t)(o*64 + c)*16 + j];
}

// ---------------- pass 1: pts, dw, 9 raw moments ----------------
__global__ void k1(const float* __restrict__ sup, const int* __restrict__ nbr,
                   const float* __restrict__ alpha_p, const float* __restrict__ beta_p,
                   const float* __restrict__ nr_p) {
    __shared__ float s_red[8*9];
    int t = threadIdx.x;
    int b = blockIdx.y;
    int m = blockIdx.x * 16 + (t >> 4);
    int k = t & 15;
    float alpha = alpha_p[0], beta = beta_p[0], inr = 1.0f / nr_p[0];

    int n = nbr[(size_t)(b*M_ + m)*KNN + k];
    float4 p = ((const float4*)g_post)[b*N_ + n];
    float sx = sup[(size_t)(b*3 + 0)*M_ + m];
    float sy = sup[(size_t)(b*3 + 1)*M_ + m];
    float sz = sup[(size_t)(b*3 + 2)*M_ + m];
    float px = p.x - sx, py = p.y - sy, pz = p.z - sz;

    float d  = sqrtf(px*px + py*py + pz*pz);
    float sg = 1.0f / (1.0f + expf(alpha*d - beta));
    float ssum = sg;
    #pragma unroll
    for (int s = 8; s >= 1; s >>= 1) ssum += __shfl_xor_sync(0xffffffffu, ssum, s);
    float dws = ssum + ((ssum == 0.0f) ? 1.0f : 0.0f) + 1e-6f;
    float dwk = sg / dws * (float)KNN;
    g_dw[(size_t)(b*M_ + m)*KNN + k] = dwk;

    px *= inr; py *= inr; pz *= inr;
    g_pts[(size_t)(b*M_ + m)*KNN + k] = make_float4(px, py, pz, 0.0f);

    float mom[9];
    mom[0]=px; mom[1]=py; mom[2]=pz;
    mom[3]=px*px; mom[4]=py*py; mom[5]=pz*pz;
    mom[6]=px*py; mom[7]=px*pz; mom[8]=py*pz;

    int lane = t & 31, wid = t >> 5;
    #pragma unroll
    for (int i = 0; i < 9; i++) {
        float v = mom[i];
        #pragma unroll
        for (int s = 16; s >= 1; s >>= 1) v += __shfl_xor_sync(0xffffffffu, v, s);
        if (lane == 0) s_red[wid*9 + i] = v;
    }
    __syncthreads();
    if (t < 9) {
        float a = 0.0f;
        #pragma unroll
        for (int w = 0; w < 8; w++) a += s_red[w*9 + t];
        g_part1[((size_t)b*NBLK1 + blockIdx.x)*16 + t] = a;
    }
}

// ---------------- stats1: analytic per-channel mean/var from moments ----------------
__global__ void k_stats1(const float* __restrict__ fc1,
                         const float* __restrict__ bnw, const float* __restrict__ bnb) {
    __shared__ float s_w[16];
    __shared__ float s_m[9];
    int b = blockIdx.x, t = threadIdx.x;   // 512 threads
    int lane = t & 31, wid = t >> 5;
    float v[9];
    #pragma unroll
    for (int i = 0; i < 9; i++) v[i] = g_part1[((size_t)b*NBLK1 + t)*16 + i];
    #pragma unroll
    for (int i = 0; i < 9; i++) {
        float r = v[i];
        #pragma unroll
        for (int s = 16; s >= 1; s >>= 1) r += __shfl_xor_sync(0xffffffffu, r, s);
        if (lane == 0) s_w[wid] = r;
        __syncthreads();
        if (t == 0) {
            float a = 0.0f;
            #pragma unroll
            for (int w = 0; w < 16; w++) a += s_w[w];
            s_m[i] = a * MK_INV;
        }
        __syncthreads();
    }
    if (t < 16) {
        float w0 = fc1[t*3], w1 = fc1[t*3+1], w2 = fc1[t*3+2];
        float mean = w0*s_m[0] + w1*s_m[1] + w2*s_m[2];
        float ev2  = w0*w0*s_m[3] + w1*w1*s_m[4] + w2*w2*s_m[5]
                   + 2.0f*(w0*w1*s_m[6] + w0*w2*s_m[7] + w1*w2*s_m[8]);
        float var  = ev2 - mean*mean;
        float rstd = rsqrtf(var + 1e-5f);
        float sc = bnw[t] * rstd;
        g_ab1[b*16 + t] = make_float2(sc, bnb[t] - mean*sc);
    }
}

// ---------------- pass 2: recompute t1, mat1, mp1, t2 = fc2@[mat1;mp1], stats ----------------
__global__ void k2(const float* __restrict__ fc1, const float* __restrict__ fc2) {
    __shared__ float s_fc1[64];       // padded [ch][4]
    __shared__ float s_fc2[512];
    __shared__ float2 s_ab[16];
    __shared__ float s_red[8*32];
    int t = threadIdx.x, b = blockIdx.y;
    s_fc2[t] = fc2[t];
    s_fc2[t + 256] = fc2[t + 256];
    if (t < 16) {
        s_fc1[t*4+0] = fc1[t*3+0];
        s_fc1[t*4+1] = fc1[t*3+1];
        s_fc1[t*4+2] = fc1[t*3+2];
        s_fc1[t*4+3] = 0.0f;
        s_ab[t] = g_ab1[b*16 + t];
    }
    __syncthreads();

    int m = blockIdx.x * 16 + (t >> 4);
    int k = t & 15;
    int lane = t & 31, wid = t >> 5;
    float4 p = g_pts[(size_t)(b*M_ + m)*KNN + k];
    float dwk = g_dw[(size_t)(b*M_ + m)*KNN + k];

    float mat1[16], mp1[16];
    const float4* f1 = (const float4*)s_fc1;
    #pragma unroll
    for (int ch = 0; ch < 16; ch++) {
        float4 w = f1[ch];
        float v = w.x*p.x + w.y*p.y + w.z*p.z;
        float2 a = s_ab[ch];
        v = fmaxf(fmaf(v, a.x, a.y), 0.0f);
        mat1[ch] = v;
        mp1[ch] = redux_max16(v * dwk, lane);
    }

    float t2v[16];
    const float4* f2 = (const float4*)s_fc2;
    #pragma unroll 4
    for (int j = 0; j < 16; j++) {
        float v = 0.0f;
        #pragma unroll
        for (int cq = 0; cq < 4; cq++) {
            float4 w = f2[j*8 + cq];
            v = fmaf(w.x, mat1[cq*4+0], v); v = fmaf(w.y, mat1[cq*4+1], v);
            v = fmaf(w.z, mat1[cq*4+2], v); v = fmaf(w.w, mat1[cq*4+3], v);
        }
        #pragma unroll
        for (int cq = 0; cq < 4; cq++) {
            float4 w = f2[j*8 + 4 + cq];
            v = fmaf(w.x, mp1[cq*4+0], v); v = fmaf(w.y, mp1[cq*4+1], v);
            v = fmaf(w.z, mp1[cq*4+2], v); v = fmaf(w.w, mp1[cq*4+3], v);
        }
        t2v[j] = v;
    }
    // store t2 layout [b][m][k][j]: 4 contiguous float4 per thread
    float4* o4 = (float4*)(g_t2 + (((size_t)(b*M_ + m)*16) + k)*16);
    o4[0] = make_float4(t2v[0], t2v[1], t2v[2], t2v[3]);
    o4[1] = make_float4(t2v[4], t2v[5], t2v[6], t2v[7]);
    o4[2] = make_float4(t2v[8], t2v[9], t2v[10], t2v[11]);
    o4[3] = make_float4(t2v[12], t2v[13], t2v[14], t2v[15]);

    // stats via partition-reduce: 31 shfl
    float stat[32];
    #pragma unroll
    for (int j = 0; j < 16; j++) { stat[j] = t2v[j]; stat[16+j] = t2v[j]*t2v[j]; }
    float r = preduce32(stat, lane);
    s_red[wid*32 + lane] = r;
    __syncthreads();
    if (t < 32) {
        float a = 0.0f;
        #pragma unroll
        for (int w = 0; w < 8; w++) a += s_red[w*32 + t];
        g_part2[((size_t)b*NBLK1 + blockIdx.x)*32 + t] = a;
    }
}

// ---------------- stats2: parallel reduction of 32 stats ----------------
__global__ void k_stats2(const float* __restrict__ bnw, const float* __restrict__ bnb) {
    __shared__ float s_p[32*32];
    __shared__ float s_c[32];
    int b = blockIdx.x, t = threadIdx.x;   // 1024 threads
    int w = t >> 5, s = t & 31;
    float a = 0.0f;
    #pragma unroll
    for (int i = 0; i < 16; i++)
        a += g_part2[((size_t)b*NBLK1 + w*16 + i)*32 + s];
    s_p[w*32 + s] = a;
    __syncthreads();
    if (t < 32) {
        float r = 0.0f;
        #pragma unroll
        for (int w2 = 0; w2 < 32; w2++) r += s_p[w2*32 + t];
        s_c[t] = r;
    }
    __syncthreads();
    if (t < 16) {
        float mean = s_c[t] * MK_INV;
        float var  = s_c[t+16] * MK_INV - mean*mean;
        float rstd = rsqrtf(var + 1e-5f);
        float sc = bnw[t] * rstd;
        g_ab2[b*16 + t] = make_float2(sc, bnb[t] - mean*sc);
    }
}

// ---------------- pass 3 (fused): mat3, gather+feat GEMM, smem-staged cv GEMM ------
// 512 threads, 32 points per block, 1 CTA/SM.
// smem floats: s_feat 32896 | s_stage 16384 (also mat3 8192) | s_fin 2048
//            | s_fc3 512 | s_ab 32 | s_idx 512
#define OF_FEAT  0
#define OF_STAGE 32896
#define OF_FIN   (32896 + 16384)
#define OF_FC3   (32896 + 16384 + 2048)
#define OF_AB    (OF_FC3 + 512)
#define OF_IDX   (OF_AB + 32)
#define K4_SMEM  ((OF_IDX + 512) * 4)

__global__ void __launch_bounds__(512, 1)
k4(const int* __restrict__ nbr, const float* __restrict__ fc3, float* __restrict__ out) {
    extern __shared__ __align__(16) float sm[];
    float* s_feat  = sm + OF_FEAT;           // 32 rows x 1028 floats
    float* s_stage = sm + OF_STAGE;          // cv stage (64KB) / phase-1 mat3
    float* s_fin   = sm + OF_FIN;            // 64 x 32 outputs
    float* s_fc3   = sm + OF_FC3;
    float* s_ab    = sm + OF_AB;
    int*   s_idx   = (int*)(sm + OF_IDX);

    int t = threadIdx.x, b = blockIdx.y;
    int m0 = blockIdx.x * PTS_;
    int lane = t & 31;

    s_fc3[t] = fc3[t & 511];
    s_idx[t] = nbr[((size_t)(b*M_) + m0)*KNN + t];
    if (t < 16) { float2 a = g_ab2[b*16 + t]; s_ab[t] = a.x; s_ab[16 + t] = a.y; }
    __syncthreads();

    // ---- phase 1: mat3[pt][k][j] (into stage area) ----
    {
        int pt = t >> 4, k = t & 15;
        int m = m0 + pt;
        float dwk = g_dw[(size_t)(b*M_ + m)*KNN + k];
        const float4* t24 = (const float4*)(g_t2 + (((size_t)(b*M_ + m)*16) + k)*16);
        float4 q0 = t24[0], q1 = t24[1], q2 = t24[2], q3 = t24[3];
        float mat2[16], mp2[16];
        mat2[0]=q0.x; mat2[1]=q0.y; mat2[2]=q0.z; mat2[3]=q0.w;
        mat2[4]=q1.x; mat2[5]=q1.y; mat2[6]=q1.z; mat2[7]=q1.w;
        mat2[8]=q2.x; mat2[9]=q2.y; mat2[10]=q2.z; mat2[11]=q2.w;
        mat2[12]=q3.x; mat2[13]=q3.y; mat2[14]=q3.z; mat2[15]=q3.w;
        #pragma unroll
        for (int ch = 0; ch < 16; ch++) {
            float v = fmaxf(fmaf(mat2[ch], s_ab[ch], s_ab[16 + ch]), 0.0f);
            mat2[ch] = v;
            mp2[ch] = redux_max16(v * dwk, lane);
        }
        const float4* f3 = (const float4*)s_fc3;
        float t3[16];
        #pragma unroll 4
        for (int j = 0; j < 16; j++) {
            float v = 0.0f;
            #pragma unroll
            for (int cq = 0; cq < 4; cq++) {
                float4 w = f3[j*8 + cq];
                v = fmaf(w.x, mat2[cq*4+0], v); v = fmaf(w.y, mat2[cq*4+1], v);
                v = fmaf(w.z, mat2[cq*4+2], v); v = fmaf(w.w, mat2[cq*4+3], v);
            }
            #pragma unroll
            for (int cq = 0; cq < 4; cq++) {
                float4 w = f3[j*8 + 4 + cq];
                v = fmaf(w.x, mp2[cq*4+0], v); v = fmaf(w.y, mp2[cq*4+1], v);
                v = fmaf(w.z, mp2[cq*4+2], v); v = fmaf(w.w, mp2[cq*4+3], v);
            }
            t3[j] = fmaxf(v, 0.0f) * dwk;
        }
        float4* sm4 = (float4*)s_stage;
        #pragma unroll
        for (int jg = 0; jg < 4; jg++)
            sm4[pt*64 + k*4 + jg] = make_float4(t3[jg*4], t3[jg*4+1], t3[jg*4+2], t3[jg*4+3]);
    }
    __syncthreads();

    // ---- phase 2: feat[pt][d = j*64 + c], packed f32x2 ----
    {
        int pt = t >> 4, cg = t & 15;           // 4 channels per thread
        ull facc2[4][8];
        #pragma unroll
        for (int i = 0; i < 4; i++)
            #pragma unroll
            for (int jp = 0; jp < 8; jp++) facc2[i][jp] = 0ull;

        const float4* xt4 = (const float4*)g_xt;
        const ulonglong2* sm2 = (const ulonglong2*)s_stage;
        #pragma unroll 2
        for (int k = 0; k < 16; k++) {
            int n = s_idx[pt*16 + k];
            float4 xv = xt4[(size_t)(b*N_ + n)*16 + cg];
            ull d0 = dup2(xv.x), d1 = dup2(xv.y), d2 = dup2(xv.z), d3 = dup2(xv.w);
            #pragma unroll
            for (int q = 0; q < 4; q++) {
                ulonglong2 mv = sm2[pt*64 + k*4 + q];
                facc2[0][2*q]   = fma2(d0, mv.x, facc2[0][2*q]);
                facc2[1][2*q]   = fma2(d1, mv.x, facc2[1][2*q]);
                facc2[2][2*q]   = fma2(d2, mv.x, facc2[2][2*q]);
                facc2[3][2*q]   = fma2(d3, mv.x, facc2[3][2*q]);
                facc2[0][2*q+1] = fma2(d0, mv.y, facc2[0][2*q+1]);
                facc2[1][2*q+1] = fma2(d1, mv.y, facc2[1][2*q+1]);
                facc2[2][2*q+1] = fma2(d2, mv.y, facc2[2][2*q+1]);
                facc2[3][2*q+1] = fma2(d3, mv.y, facc2[3][2*q+1]);
            }
        }
        float4* sf4 = (float4*)s_feat;
        #pragma unroll
        for (int jp = 0; jp < 8; jp++) {
            float2 a0 = unpack2(facc2[0][jp]);
            float2 a1 = unpack2(facc2[1][jp]);
            float2 a2 = unpack2(facc2[2][jp]);
            float2 a3 = unpack2(facc2[3][jp]);
            sf4[pt*FS4 + (2*jp)  *16 + cg] = make_float4(a0.x, a1.x, a2.x, a3.x);
            sf4[pt*FS4 + (2*jp+1)*16 + cg] = make_float4(a0.y, a1.y, a2.y, a3.y);
        }
    }
    __syncthreads();   // mat3 dead; stage buffer free for cv

    // ---- phase 3: cv GEMM with smem-staged cv (4 chunks of 16 o) ----
    {
        int warp = t >> 5;
        int og = warp >> 2;                 // 0..3: o-subgroup within chunk
        int pg = warp & 3;                  // 0..3: p-group (8 points each)
        const uint4* cvsrc = (const uint4*)g_cvP;
        uint4* stg4 = (uint4*)s_stage;
        const ulonglong2* st2 = (const ulonglong2*)s_stage;
        const ulonglong2* sf2 = (const ulonglong2*)s_feat;

        #pragma unroll 1
        for (int oc = 0; oc < 4; oc++) {
            // cooperative stage: cv rows [oc*16, oc*16+16) = 64 KB, coalesced
            #pragma unroll
            for (int i = 0; i < 8; i++)
                stg4[t + i*512] = cvsrc[(size_t)oc*4096 + t + i*512];
            __syncthreads();

            ull acc[4][8];
            #pragma unroll
            for (int oi = 0; oi < 4; oi++)
                #pragma unroll
                for (int pi = 0; pi < 8; pi++) acc[oi][pi] = 0ull;

            #pragma unroll 1
            for (int s = 0; s < 8; s++) {
                ulonglong2 wv0 = st2[(og*4 + 0)*256 + s*32 + lane];
                ulonglong2 wv1 = st2[(og*4 + 1)*256 + s*32 + lane];
                ulonglong2 wv2 = st2[(og*4 + 2)*256 + s*32 + lane];
                ulonglong2 wv3 = st2[(og*4 + 3)*256 + s*32 + lane];
                const ulonglong2* fp = sf2 + pg*8*FS4 + s*32 + lane;
                #pragma unroll
                for (int pi = 0; pi < 8; pi++) {
                    ulonglong2 fv = fp[pi*FS4];
                    acc[0][pi] = fma2(wv0.x, fv.x, acc[0][pi]);
                    acc[0][pi] = fma2(wv0.y, fv.y, acc[0][pi]);
                    acc[1][pi] = fma2(wv1.x, fv.x, acc[1][pi]);
                    acc[1][pi] = fma2(wv1.y, fv.y, acc[1][pi]);
                    acc[2][pi] = fma2(wv2.x, fv.x, acc[2][pi]);
                    acc[2][pi] = fma2(wv2.y, fv.y, acc[2][pi]);
                    acc[3][pi] = fma2(wv3.x, fv.x, acc[3][pi]);
                    acc[3][pi] = fma2(wv3.y, fv.y, acc[3][pi]);
                }
            }
            // partition-reduce 32 (oi,pi) partials: lane l -> (oi = l>>3, pi = l&7)
            float v[32];
            #pragma unroll
            for (int oi = 0; oi < 4; oi++)
                #pragma unroll
                for (int pi = 0; pi < 8; pi++) {
                    float2 h = unpack2(acc[oi][pi]);
                    v[oi*8 + pi] = h.x + h.y;
                }
            float r = preduce32(v, lane);
            s_fin[(oc*16 + og*4 + (lane >> 3))*32 + pg*8 + (lane & 7)] = r;
            __syncthreads();   // stage reuse guard
        }
    }

    // coalesced output write: 64 o x 32 p = 2048 floats, 512 threads x float4
    {
        int o = t >> 3, pq = t & 7;
        float4 v = ((const float4*)s_fin)[o*8 + pq];
        ((float4*)out)[((size_t)(b*64 + o))*2048 + (m0 >> 2) + pq] = v;
    }
}

// ---------------- launch ----------------
extern "C" void kernel_launch(void* const* d_in, const int* in_sizes, int n_in,
                              void* d_out, int out_size) {
    const float* x     = (const float*)d_in[0];
    const float* pos   = (const float*)d_in[1];
    const float* sup   = (const float*)d_in[2];
    const int*   nbr   = (const int*)  d_in[3];
    const float* alpha = (const float*)d_in[4];
    const float* beta  = (const float*)d_in[5];
    const float* nr    = (const float*)d_in[6];
    const float* fc1   = (const float*)d_in[7];
    const float* fc2   = (const float*)d_in[8];
    const float* fc3   = (const float*)d_in[9];
    const float* bn1w  = (const float*)d_in[10];
    const float* bn1b  = (const float*)d_in[11];
    const float* bn2w  = (const float*)d_in[12];
    const float* bn2b  = (const float*)d_in[13];
    const float* cvw   = (const float*)d_in[14];
    float* out = (float*)d_out;

    cudaFuncSetAttribute((const void*)k4, cudaFuncAttributeMaxDynamicSharedMemorySize, K4_SMEM);

    k_xt    <<<dim3(N_/32, C_/32, B_), dim3(32, 8)>>>(x);
    k_pos   <<<dim3(N_/256, B_), 256>>>(pos);
    k_cvp   <<<256, 256>>>(cvw);
    k1      <<<dim3(NBLK1, B_), 256>>>(sup, nbr, alpha, beta, nr);
    k_stats1<<<B_, 512>>>(fc1, bn1w, bn1b);
    k2      <<<dim3(NBLK1, B_), 256>>>(fc1, fc2);
    k_stats2<<<B_, 1024>>>(bn2w, bn2b);
    k4      <<<dim3(M_/PTS_, B_), 512, K4_SMEM>>>(nbr, fc3, out);
}

// round 13
// speedup vs baseline: 1.1081x; 1.1081x over previous
#include <cuda_runtime.h>
#include <stdint.h>
#include <math.h>

// Problem constants (fixed by setup_inputs)
#define B_   4
#define N_   8192
#define M_   8192
#define KNN  16
#define C_   64
#define NBLK1 512
#define MK_INV (1.0f/((float)M_*(float)KNN))
#define FS4  257   // padded feat row stride in float4 / ulonglong2 units (1028 floats)
#define PTS_ 16    // points per k4 block

typedef unsigned long long ull;

// ---------------- packed f32x2 helpers (Blackwell base ISA) ----------------
__device__ __forceinline__ ull fma2(ull a, ull b, ull c) {
    ull d;
    asm("fma.rn.f32x2 %0, %1, %2, %3;" : "=l"(d) : "l"(a), "l"(b), "l"(c));
    return d;
}
__device__ __forceinline__ ull dup2(float x) {
    ull r;
    asm("mov.b64 %0, {%1, %2};" : "=l"(r) : "f"(x), "f"(x));
    return r;
}
__device__ __forceinline__ float2 unpack2(ull v) {
    float2 f;
    asm("mov.b64 {%0, %1}, %2;" : "=f"(f.x), "=f"(f.y) : "l"(v));
    return f;
}

// Partition-reduce 32 values across 32 lanes: 31 shfl total.
// On return, lane l holds the full sum of value index l.
__device__ __forceinline__ float preduce32(float* v, int lane) {
    #pragma unroll
    for (int m = 16; m >= 1; m >>= 1) {
        bool b = (lane & m) != 0;
        #pragma unroll
        for (int i = 0; i < m; i++) {
            float send = b ? v[i] : v[i + m];
            float r = __shfl_xor_sync(0xffffffffu, send, m);
            v[i] = (b ? v[i + m] : v[i]) + r;
        }
    }
    return v[0];
}

// ---------------- device scratch ----------------
__device__ float  g_xt  [B_*N_*C_];        // x transposed: [B][N][64]
__device__ float  g_post[B_*N_*4];         // pos transposed+padded
__device__ float4 g_pts [B_*M_*KNN];       // normalized pts per neighbor
__device__ float  g_dw  [B_*M_*KNN];       // distance weights
__device__ float  g_t2  [(size_t)B_*M_*256]; // fc2 out, layout [b][m][k][j]
__device__ float  g_part1[B_*NBLK1*16];
__device__ float  g_part2[B_*NBLK1*32];
__device__ float2 g_ab1[B_*16];
__device__ float2 g_ab2[B_*16];
__device__ __align__(16) float g_cvP[64*1024];  // cv repacked [o][d], d=j*64+c
__device__ unsigned g_cnt1[B_];
__device__ unsigned g_cnt2[B_];

// ---------------- fused prep: x transpose + pos transpose + cv repack + cnt reset ----
// grid: 2432 blocks x 256 threads
//   [0,2048)    x transpose (b = bid>>9, cblk = (bid>>8)&1, nblk = bid&255)
//   [2048,2176) pos transpose (b = r>>5, nblk = r&31)
//   [2176,2432) cv repack
__global__ void k_prep(const float* __restrict__ x, const float* __restrict__ pos,
                       const float* __restrict__ cv) {
    __shared__ float tile[32][33];
    int bid = blockIdx.x;
    int t = threadIdx.x;
    if (bid == 0 && t < 8) {
        if (t < 4) g_cnt1[t] = 0u;
        else       g_cnt2[t - 4] = 0u;
    }
    if (bid < 2048) {
        int b    = bid >> 9;
        int c0   = ((bid >> 8) & 1) * 32;
        int n0   = (bid & 255) * 32;
        int tx = t & 31, ty = t >> 5;        // 32 x 8
        #pragma unroll
        for (int i = 0; i < 32; i += 8)
            tile[ty + i][tx] = x[(size_t)(b*C_ + c0 + ty + i)*N_ + n0 + tx];
        __syncthreads();
        #pragma unroll
        for (int i = 0; i < 32; i += 8)
            g_xt[(size_t)(b*N_ + n0 + ty + i)*C_ + c0 + tx] = tile[tx][ty + i];
    } else if (bid < 2176) {
        int r = bid - 2048;
        int b = r >> 5;
        int n = (r & 31) * 256 + t;
        float4 v;
        v.x = pos[(size_t)(b*3 + 0)*N_ + n];
        v.y = pos[(size_t)(b*3 + 1)*N_ + n];
        v.z = pos[(size_t)(b*3 + 2)*N_ + n];
        v.w = 0.0f;
        ((float4*)g_post)[b*N_ + n] = v;
    } else {
        int g = (bid - 2176) * 256 + t;      // 65536
        int o = g >> 10;
        int d = g & 1023;
        int c = d & 63;
        int j = d >> 6;
        g_cvP[g] = cv[(size_t)(o*64 + c)*16 + j];
    }
}

// ---------------- pass 1: pts, dw, 9 raw moments; last block computes ab1 ----------
__global__ void k1(const float* __restrict__ sup, const int* __restrict__ nbr,
                   const float* __restrict__ alpha_p, const float* __restrict__ beta_p,
                   const float* __restrict__ nr_p, const float* __restrict__ fc1,
                   const float* __restrict__ bnw, const float* __restrict__ bnb) {
    __shared__ float s_red[8*9];
    int t = threadIdx.x;
    int b = blockIdx.y;
    int m = blockIdx.x * 16 + (t >> 4);
    int k = t & 15;
    float alpha = alpha_p[0], beta = beta_p[0], inr = 1.0f / nr_p[0];

    int n = nbr[(size_t)(b*M_ + m)*KNN + k];
    float4 p = ((const float4*)g_post)[b*N_ + n];
    float sx = sup[(size_t)(b*3 + 0)*M_ + m];
    float sy = sup[(size_t)(b*3 + 1)*M_ + m];
    float sz = sup[(size_t)(b*3 + 2)*M_ + m];
    float px = p.x - sx, py = p.y - sy, pz = p.z - sz;

    float d  = sqrtf(px*px + py*py + pz*pz);
    float sg = 1.0f / (1.0f + expf(alpha*d - beta));
    float ssum = sg;
    #pragma unroll
    for (int s = 8; s >= 1; s >>= 1) ssum += __shfl_xor_sync(0xffffffffu, ssum, s);
    float dws = ssum + ((ssum == 0.0f) ? 1.0f : 0.0f) + 1e-6f;
    float dwk = sg / dws * (float)KNN;
    g_dw[(size_t)(b*M_ + m)*KNN + k] = dwk;

    px *= inr; py *= inr; pz *= inr;
    g_pts[(size_t)(b*M_ + m)*KNN + k] = make_float4(px, py, pz, 0.0f);

    float mom[9];
    mom[0]=px; mom[1]=py; mom[2]=pz;
    mom[3]=px*px; mom[4]=py*py; mom[5]=pz*pz;
    mom[6]=px*py; mom[7]=px*pz; mom[8]=py*pz;

    int lane = t & 31, wid = t >> 5;
    #pragma unroll
    for (int i = 0; i < 9; i++) {
        float v = mom[i];
        #pragma unroll
        for (int s = 16; s >= 1; s >>= 1) v += __shfl_xor_sync(0xffffffffu, v, s);
        if (lane == 0) s_red[wid*9 + i] = v;
    }
    __syncthreads();
    if (t < 9) {
        float a = 0.0f;
        #pragma unroll
        for (int w = 0; w < 8; w++) a += s_red[w*9 + t];
        g_part1[((size_t)b*NBLK1 + blockIdx.x)*16 + t] = a;
    }
    // ---- last-block finalize: analytic per-channel mean/var -> ab1 ----
    __syncthreads();
    __threadfence();
    __shared__ unsigned s_last;
    if (t == 0) s_last = (atomicAdd(&g_cnt1[b], 1u) == (unsigned)(NBLK1 - 1)) ? 1u : 0u;
    __syncthreads();
    if (s_last) {
        __shared__ float s_w[8];
        __shared__ float s_m[9];
        #pragma unroll 1
        for (int i = 0; i < 9; i++) {
            float r = g_part1[((size_t)b*NBLK1 + t)*16 + i]
                    + g_part1[((size_t)b*NBLK1 + t + 256)*16 + i];
            #pragma unroll
            for (int s = 16; s >= 1; s >>= 1) r += __shfl_xor_sync(0xffffffffu, r, s);
            if (lane == 0) s_w[wid] = r;
            __syncthreads();
            if (t == 0) {
                float a = 0.0f;
                #pragma unroll
                for (int w = 0; w < 8; w++) a += s_w[w];
                s_m[i] = a * MK_INV;
            }
            __syncthreads();
        }
        if (t < 16) {
            float w0 = fc1[t*3], w1 = fc1[t*3+1], w2 = fc1[t*3+2];
            float mean = w0*s_m[0] + w1*s_m[1] + w2*s_m[2];
            float ev2  = w0*w0*s_m[3] + w1*w1*s_m[4] + w2*w2*s_m[5]
                       + 2.0f*(w0*w1*s_m[6] + w0*w2*s_m[7] + w1*w2*s_m[8]);
            float var  = ev2 - mean*mean;
            float rstd = rsqrtf(var + 1e-5f);
            float sc = bnw[t] * rstd;
            g_ab1[b*16 + t] = make_float2(sc, bnb[t] - mean*sc);
        }
    }
}

// ---------------- pass 2: t1, mat1, mp1, t2 = fc2@[mat1;mp1]; last block -> ab2 -----
__global__ void k2(const float* __restrict__ fc1, const float* __restrict__ fc2,
                   const float* __restrict__ bnw, const float* __restrict__ bnb) {
    __shared__ float s_fc1[64];       // padded [ch][4]
    __shared__ float s_fc2[512];
    __shared__ float2 s_ab[16];
    __shared__ float s_red[8*32];
    int t = threadIdx.x, b = blockIdx.y;
    s_fc2[t] = fc2[t];
    s_fc2[t + 256] = fc2[t + 256];
    if (t < 16) {
        s_fc1[t*4+0] = fc1[t*3+0];
        s_fc1[t*4+1] = fc1[t*3+1];
        s_fc1[t*4+2] = fc1[t*3+2];
        s_fc1[t*4+3] = 0.0f;
        s_ab[t] = g_ab1[b*16 + t];
    }
    __syncthreads();

    int m = blockIdx.x * 16 + (t >> 4);
    int k = t & 15;
    int lane = t & 31, wid = t >> 5;
    float4 p = g_pts[(size_t)(b*M_ + m)*KNN + k];
    float dwk = g_dw[(size_t)(b*M_ + m)*KNN + k];

    float mat1[16], mp1[16];
    const float4* f1 = (const float4*)s_fc1;
    #pragma unroll
    for (int ch = 0; ch < 16; ch++) {
        float4 w = f1[ch];
        float v = w.x*p.x + w.y*p.y + w.z*p.z;
        float2 a = s_ab[ch];
        v = fmaxf(fmaf(v, a.x, a.y), 0.0f);
        mat1[ch] = v;
        float wmax = v * dwk;
        #pragma unroll
        for (int s = 8; s >= 1; s >>= 1) wmax = fmaxf(wmax, __shfl_xor_sync(0xffffffffu, wmax, s));
        mp1[ch] = wmax;
    }

    float t2v[16];
    const float4* f2 = (const float4*)s_fc2;
    #pragma unroll 4
    for (int j = 0; j < 16; j++) {
        float v = 0.0f;
        #pragma unroll
        for (int cq = 0; cq < 4; cq++) {
            float4 w = f2[j*8 + cq];
            v = fmaf(w.x, mat1[cq*4+0], v); v = fmaf(w.y, mat1[cq*4+1], v);
            v = fmaf(w.z, mat1[cq*4+2], v); v = fmaf(w.w, mat1[cq*4+3], v);
        }
        #pragma unroll
        for (int cq = 0; cq < 4; cq++) {
            float4 w = f2[j*8 + 4 + cq];
            v = fmaf(w.x, mp1[cq*4+0], v); v = fmaf(w.y, mp1[cq*4+1], v);
            v = fmaf(w.z, mp1[cq*4+2], v); v = fmaf(w.w, mp1[cq*4+3], v);
        }
        t2v[j] = v;
    }
    // store t2 layout [b][m][k][j]: 4 contiguous float4 per thread
    float4* o4 = (float4*)(g_t2 + (((size_t)(b*M_ + m)*16) + k)*16);
    o4[0] = make_float4(t2v[0], t2v[1], t2v[2], t2v[3]);
    o4[1] = make_float4(t2v[4], t2v[5], t2v[6], t2v[7]);
    o4[2] = make_float4(t2v[8], t2v[9], t2v[10], t2v[11]);
    o4[3] = make_float4(t2v[12], t2v[13], t2v[14], t2v[15]);

    // stats via partition-reduce: 31 shfl
    float stat[32];
    #pragma unroll
    for (int j = 0; j < 16; j++) { stat[j] = t2v[j]; stat[16+j] = t2v[j]*t2v[j]; }
    float r = preduce32(stat, lane);
    s_red[wid*32 + lane] = r;
    __syncthreads();
    if (t < 32) {
        float a = 0.0f;
        #pragma unroll
        for (int w = 0; w < 8; w++) a += s_red[w*32 + t];
        g_part2[((size_t)b*NBLK1 + blockIdx.x)*32 + t] = a;
    }
    // ---- last-block finalize -> ab2 ----
    __syncthreads();
    __threadfence();
    __shared__ unsigned s_last;
    if (t == 0) s_last = (atomicAdd(&g_cnt2[b], 1u) == (unsigned)(NBLK1 - 1)) ? 1u : 0u;
    __syncthreads();
    if (s_last) {
        __shared__ float s_p[8*32];
        __shared__ float s_c[32];
        float a0 = 0.0f, a1 = 0.0f, a2 = 0.0f, a3 = 0.0f;
        #pragma unroll 4
        for (int i = 0; i < 16; i++) {
            a0 += g_part2[((size_t)b*NBLK1 + wid*64 + i)*32 + lane];
            a1 += g_part2[((size_t)b*NBLK1 + wid*64 + 16 + i)*32 + lane];
            a2 += g_part2[((size_t)b*NBLK1 + wid*64 + 32 + i)*32 + lane];
            a3 += g_part2[((size_t)b*NBLK1 + wid*64 + 48 + i)*32 + lane];
        }
        s_p[wid*32 + lane] = (a0 + a1) + (a2 + a3);
        __syncthreads();
        if (t < 32) {
            float rr = 0.0f;
            #pragma unroll
            for (int w = 0; w < 8; w++) rr += s_p[w*32 + t];
            s_c[t] = rr;
        }
        __syncthreads();
        if (t < 16) {
            float mean = s_c[t] * MK_INV;
            float var  = s_c[t+16] * MK_INV - mean*mean;
            float rstd = rsqrtf(var + 1e-5f);
            float sc = bnw[t] * rstd;
            g_ab2[b*16 + t] = make_float2(sc, bnb[t] - mean*sc);
        }
    }
}

// ---------------- pass 3 (fused): mat3, gather+feat GEMM, cv GEMM ----------------
// 256 threads, 16 points per block, 2 CTAs/SM.  (exact R11 body)
// smem floats: s_feat 16448 | s_mat3 4096 | s_fc3 512 | s_ab 32 | s_idx 256i
#define K4_SMEM ((16448 + 4096 + 512 + 32 + 256) * 4)

__global__ void __launch_bounds__(256, 2)
k4(const int* __restrict__ nbr, const float* __restrict__ fc3, float* __restrict__ out) {
    extern __shared__ __align__(16) float sm[];
    float* s_feat = sm;                          // 16448 floats (16 rows x 1028)
    float* s_mat3 = sm + 16448;                  // 4096 (also reused as s_fin)
    float* s_fc3  = sm + 16448 + 4096;           // 512
    float* s_ab   = sm + 16448 + 4096 + 512;     // 32
    int*   s_idx  = (int*)(sm + 16448 + 4096 + 512 + 32); // 256

    int t = threadIdx.x, b = blockIdx.y;
    int m0 = blockIdx.x * PTS_;

    s_fc3[t] = fc3[t];
    s_fc3[t + 256] = fc3[t + 256];
    s_idx[t] = nbr[((size_t)(b*M_) + m0)*KNN + t];
    if (t < 16) { float2 a = g_ab2[b*16 + t]; s_ab[t] = a.x; s_ab[16 + t] = a.y; }
    __syncthreads();

    // ---- phase 1: mat3[pt][k][j] ----
    {
        int pt = t >> 4, k = t & 15;
        int m = m0 + pt;
        float dwk = g_dw[(size_t)(b*M_ + m)*KNN + k];
        const float4* t24 = (const float4*)(g_t2 + (((size_t)(b*M_ + m)*16) + k)*16);
        float4 q0 = t24[0], q1 = t24[1], q2 = t24[2], q3 = t24[3];
        float mat2[16], mp2[16];
        mat2[0]=q0.x; mat2[1]=q0.y; mat2[2]=q0.z; mat2[3]=q0.w;
        mat2[4]=q1.x; mat2[5]=q1.y; mat2[6]=q1.z; mat2[7]=q1.w;
        mat2[8]=q2.x; mat2[9]=q2.y; mat2[10]=q2.z; mat2[11]=q2.w;
        mat2[12]=q3.x; mat2[13]=q3.y; mat2[14]=q3.z; mat2[15]=q3.w;
        #pragma unroll
        for (int ch = 0; ch < 16; ch++) {
            float v = fmaxf(fmaf(mat2[ch], s_ab[ch], s_ab[16 + ch]), 0.0f);
            mat2[ch] = v;
            float w = v * dwk;
            #pragma unroll
            for (int s = 8; s >= 1; s >>= 1) w = fmaxf(w, __shfl_xor_sync(0xffffffffu, w, s));
            mp2[ch] = w;
        }
        const float4* f3 = (const float4*)s_fc3;
        float t3[16];
        #pragma unroll 4
        for (int j = 0; j < 16; j++) {
            float v = 0.0f;
            #pragma unroll
            for (int cq = 0; cq < 4; cq++) {
                float4 w = f3[j*8 + cq];
                v = fmaf(w.x, mat2[cq*4+0], v); v = fmaf(w.y, mat2[cq*4+1], v);
                v = fmaf(w.z, mat2[cq*4+2], v); v = fmaf(w.w, mat2[cq*4+3], v);
            }
            #pragma unroll
            for (int cq = 0; cq < 4; cq++) {
                float4 w = f3[j*8 + 4 + cq];
                v = fmaf(w.x, mp2[cq*4+0], v); v = fmaf(w.y, mp2[cq*4+1], v);
                v = fmaf(w.z, mp2[cq*4+2], v); v = fmaf(w.w, mp2[cq*4+3], v);
            }
            t3[j] = fmaxf(v, 0.0f) * dwk;
        }
        float4* sm4 = (float4*)s_mat3;
        #pragma unroll
        for (int jg = 0; jg < 4; jg++)
            sm4[pt*64 + k*4 + jg] = make_float4(t3[jg*4], t3[jg*4+1], t3[jg*4+2], t3[jg*4+3]);
    }
    __syncthreads();

    // ---- phase 2: feat[pt][d = j*64 + c], packed f32x2 ----
    {
        int pt = t >> 4, cg = t & 15;           // 4 channels per thread
        ull facc2[4][8];
        #pragma unroll
        for (int i = 0; i < 4; i++)
            #pragma unroll
            for (int jp = 0; jp < 8; jp++) facc2[i][jp] = 0ull;

        const float4* xt4 = (const float4*)g_xt;
        const ulonglong2* sm2 = (const ulonglong2*)s_mat3;
        #pragma unroll 2
        for (int k = 0; k < 16; k++) {
            int n = s_idx[pt*16 + k];
            float4 xv = xt4[(size_t)(b*N_ + n)*16 + cg];
            ull d0 = dup2(xv.x), d1 = dup2(xv.y), d2 = dup2(xv.z), d3 = dup2(xv.w);
            #pragma unroll
            for (int q = 0; q < 4; q++) {
                ulonglong2 mv = sm2[pt*64 + k*4 + q];
                facc2[0][2*q]   = fma2(d0, mv.x, facc2[0][2*q]);
                facc2[1][2*q]   = fma2(d1, mv.x, facc2[1][2*q]);
                facc2[2][2*q]   = fma2(d2, mv.x, facc2[2][2*q]);
                facc2[3][2*q]   = fma2(d3, mv.x, facc2[3][2*q]);
                facc2[0][2*q+1] = fma2(d0, mv.y, facc2[0][2*q+1]);
                facc2[1][2*q+1] = fma2(d1, mv.y, facc2[1][2*q+1]);
                facc2[2][2*q+1] = fma2(d2, mv.y, facc2[2][2*q+1]);
                facc2[3][2*q+1] = fma2(d3, mv.y, facc2[3][2*q+1]);
            }
        }
        float4* sf4 = (float4*)s_feat;
        #pragma unroll
        for (int jp = 0; jp < 8; jp++) {
            float2 a0 = unpack2(facc2[0][jp]);
            float2 a1 = unpack2(facc2[1][jp]);
            float2 a2 = unpack2(facc2[2][jp]);
            float2 a3 = unpack2(facc2[3][jp]);
            sf4[pt*FS4 + (2*jp)  *16 + cg] = make_float4(a0.x, a1.x, a2.x, a3.x);
            sf4[pt*FS4 + (2*jp+1)*16 + cg] = make_float4(a0.y, a1.y, a2.y, a3.y);
        }
    }
    __syncthreads();

    // ---- phase 3: out[o][p] = dot(cv2[o], feat[p]), lane-over-d, partition-reduce ----
    {
        int warp = t >> 5, lane = t & 31;
        int g    = warp >> 1;                   // o group 0..3
        int pbase = (warp & 1) * 8;             // 8 points per warp
        const ulonglong2* cv2 = (const ulonglong2*)g_cvP;
        const ulonglong2* sf2 = (const ulonglong2*)s_feat;
        float* s_fin = s_mat3;                  // reuse: [o][p] 64x16

        #pragma unroll 1
        for (int it = 0; it < 4; it++) {
            int obase = g*4 + it*16;
            ull acc[4][8];
            #pragma unroll
            for (int oi = 0; oi < 4; oi++)
                #pragma unroll
                for (int pi = 0; pi < 8; pi++) acc[oi][pi] = 0ull;

            #pragma unroll 1
            for (int s = 0; s < 8; s++) {
                ulonglong2 wv0 = cv2[(obase + 0)*256 + s*32 + lane];
                ulonglong2 wv1 = cv2[(obase + 1)*256 + s*32 + lane];
                ulonglong2 wv2 = cv2[(obase + 2)*256 + s*32 + lane];
                ulonglong2 wv3 = cv2[(obase + 3)*256 + s*32 + lane];
                const ulonglong2* fp = sf2 + pbase*FS4 + s*32 + lane;
                #pragma unroll
                for (int pi = 0; pi < 8; pi++) {
                    ulonglong2 fv = fp[pi*FS4];
                    acc[0][pi] = fma2(wv0.x, fv.x, acc[0][pi]);
                    acc[0][pi] = fma2(wv0.y, fv.y, acc[0][pi]);
                    acc[1][pi] = fma2(wv1.x, fv.x, acc[1][pi]);
                    acc[1][pi] = fma2(wv1.y, fv.y, acc[1][pi]);
                    acc[2][pi] = fma2(wv2.x, fv.x, acc[2][pi]);
                    acc[2][pi] = fma2(wv2.y, fv.y, acc[2][pi]);
                    acc[3][pi] = fma2(wv3.x, fv.x, acc[3][pi]);
                    acc[3][pi] = fma2(wv3.y, fv.y, acc[3][pi]);
                }
            }
            // partition-reduce the 32 (oi,pi) partial sums: 31 shfl, lane l ends
            // with the full sum for output index l (oi = l>>3, pi = l&7)
            float v[32];
            #pragma unroll
            for (int oi = 0; oi < 4; oi++)
                #pragma unroll
                for (int pi = 0; pi < 8; pi++) {
                    float2 h = unpack2(acc[oi][pi]);
                    v[oi*8 + pi] = h.x + h.y;
                }
            float r = preduce32(v, lane);
            s_fin[(obase + (lane >> 3))*16 + pbase + (lane & 7)] = r;
        }
    }
    __syncthreads();

    // coalesced output write: 64 o x 16 p = 1024 floats, 256 threads x float4
    {
        int o = t >> 2, pq = t & 3;
        float4 v = ((const float4*)s_mat3)[o*4 + pq];
        ((float4*)out)[((size_t)(b*64 + o))*2048 + (m0 >> 2) + pq] = v;
    }
}

// ---------------- launch ----------------
extern "C" void kernel_launch(void* const* d_in, const int* in_sizes, int n_in,
                              void* d_out, int out_size) {
    const float* x     = (const float*)d_in[0];
    const float* pos   = (const float*)d_in[1];
    const float* sup   = (const float*)d_in[2];
    const int*   nbr   = (const int*)  d_in[3];
    const float* alpha = (const float*)d_in[4];
    const float* beta  = (const float*)d_in[5];
    const float* nr    = (const float*)d_in[6];
    const float* fc1   = (const float*)d_in[7];
    const float* fc2   = (const float*)d_in[8];
    const float* fc3   = (const float*)d_in[9];
    const float* bn1w  = (const float*)d_in[10];
    const float* bn1b  = (const float*)d_in[11];
    const float* bn2w  = (const float*)d_in[12];
    const float* bn2b  = (const float*)d_in[13];
    const float* cvw   = (const float*)d_in[14];
    float* out = (float*)d_out;

    cudaFuncSetAttribute((const void*)k4, cudaFuncAttributeMaxDynamicSharedMemorySize, K4_SMEM);

    k_prep<<<2432, 256>>>(x, pos, cvw);
    k1    <<<dim3(NBLK1, B_), 256>>>(sup, nbr, alpha, beta, nr, fc1, bn1w, bn1b);
    k2    <<<dim3(NBLK1, B_), 256>>>(fc1, fc2, bn2w, bn2b);
    k4    <<<dim3(M_/PTS_, B_), 256, K4_SMEM>>>(nbr, fc3, out);
}

// round 14
// speedup vs baseline: 1.2027x; 1.0854x over previous
#include <cuda_runtime.h>
#include <stdint.h>
#include <math.h>

// Problem constants (fixed by setup_inputs)
#define B_   4
#define N_   8192
#define M_   8192
#define KNN  16
#define C_   64
#define NBLK1 512
#define MK_INV (1.0f/((float)M_*(float)KNN))
#define FS4  257   // padded feat row stride in float4 units (1028 floats)
#define FSF  1028  // padded feat row stride in floats
#define PTS_ 16    // points per k4 block

typedef unsigned long long ull;

// ---------------- packed f32x2 helpers (Blackwell base ISA) ----------------
__device__ __forceinline__ ull fma2(ull a, ull b, ull c) {
    ull d;
    asm("fma.rn.f32x2 %0, %1, %2, %3;" : "=l"(d) : "l"(a), "l"(b), "l"(c));
    return d;
}
__device__ __forceinline__ ull dup2(float x) {
    ull r;
    asm("mov.b64 %0, {%1, %2};" : "=l"(r) : "f"(x), "f"(x));
    return r;
}
__device__ __forceinline__ float2 unpack2(ull v) {
    float2 f;
    asm("mov.b64 {%0, %1}, %2;" : "=f"(f.x), "=f"(f.y) : "l"(v));
    return f;
}

// Partition-reduce 32 values across 32 lanes: 31 shfl total.
// On return, lane l holds the full sum of value index l.
__device__ __forceinline__ float preduce32(float* v, int lane) {
    #pragma unroll
    for (int m = 16; m >= 1; m >>= 1) {
        bool b = (lane & m) != 0;
        #pragma unroll
        for (int i = 0; i < m; i++) {
            float send = b ? v[i] : v[i + m];
            float r = __shfl_xor_sync(0xffffffffu, send, m);
            v[i] = (b ? v[i + m] : v[i]) + r;
        }
    }
    return v[0];
}

// ---------------- device scratch ----------------
__device__ float  g_xt  [B_*N_*C_];        // x transposed: [B][N][64]
__device__ float  g_post[B_*N_*4];         // pos transposed+padded
__device__ float4 g_pts [B_*M_*KNN];       // normalized pts per neighbor
__device__ float  g_dw  [B_*M_*KNN];       // distance weights
__device__ float  g_t2  [(size_t)B_*M_*256]; // fc2 out, layout [b][m][k][j]
__device__ float  g_part1[B_*NBLK1*16];
__device__ float  g_part2[B_*NBLK1*32];
__device__ float2 g_ab1[B_*16];
__device__ float2 g_ab2[B_*16];
// cv repacked as o-pairs: cvP2[(op*1024 + d)*2 + e] = cv row o=2*op+e at dim d (d=j*64+c)
__device__ __align__(16) float g_cvP[64*1024];
__device__ unsigned g_cnt1[B_];
__device__ unsigned g_cnt2[B_];

// ---------------- fused prep: x transpose + pos transpose + cv repack + cnt reset ----
__global__ void k_prep(const float* __restrict__ x, const float* __restrict__ pos,
                       const float* __restrict__ cv) {
    __shared__ float tile[32][33];
    int bid = blockIdx.x;
    int t = threadIdx.x;
    if (bid == 0 && t < 8) {
        if (t < 4) g_cnt1[t] = 0u;
        else       g_cnt2[t - 4] = 0u;
    }
    if (bid < 2048) {
        int b    = bid >> 9;
        int c0   = ((bid >> 8) & 1) * 32;
        int n0   = (bid & 255) * 32;
        int tx = t & 31, ty = t >> 5;        // 32 x 8
        #pragma unroll
        for (int i = 0; i < 32; i += 8)
            tile[ty + i][tx] = x[(size_t)(b*C_ + c0 + ty + i)*N_ + n0 + tx];
        __syncthreads();
        #pragma unroll
        for (int i = 0; i < 32; i += 8)
            g_xt[(size_t)(b*N_ + n0 + ty + i)*C_ + c0 + tx] = tile[tx][ty + i];
    } else if (bid < 2176) {
        int r = bid - 2048;
        int b = r >> 5;
        int n = (r & 31) * 256 + t;
        float4 v;
        v.x = pos[(size_t)(b*3 + 0)*N_ + n];
        v.y = pos[(size_t)(b*3 + 1)*N_ + n];
        v.z = pos[(size_t)(b*3 + 2)*N_ + n];
        v.w = 0.0f;
        ((float4*)g_post)[b*N_ + n] = v;
    } else {
        int g = (bid - 2176) * 256 + t;      // 65536
        int o = g >> 10;
        int d = g & 1023;
        int c = d & 63;
        int j = d >> 6;
        g_cvP[((size_t)(o >> 1)*1024 + d)*2 + (o & 1)] = cv[(size_t)(o*64 + c)*16 + j];
    }
}

// ---------------- pass 1: pts, dw, 9 raw moments; last block computes ab1 ----------
__global__ void k1(const float* __restrict__ sup, const int* __restrict__ nbr,
                   const float* __restrict__ alpha_p, const float* __restrict__ beta_p,
                   const float* __restrict__ nr_p, const float* __restrict__ fc1,
                   const float* __restrict__ bnw, const float* __restrict__ bnb) {
    __shared__ float s_red[8*9];
    int t = threadIdx.x;
    int b = blockIdx.y;
    int m = blockIdx.x * 16 + (t >> 4);
    int k = t & 15;
    float alpha = alpha_p[0], beta = beta_p[0], inr = 1.0f / nr_p[0];

    int n = nbr[(size_t)(b*M_ + m)*KNN + k];
    float4 p = ((const float4*)g_post)[b*N_ + n];
    float sx = sup[(size_t)(b*3 + 0)*M_ + m];
    float sy = sup[(size_t)(b*3 + 1)*M_ + m];
    float sz = sup[(size_t)(b*3 + 2)*M_ + m];
    float px = p.x - sx, py = p.y - sy, pz = p.z - sz;

    float d  = sqrtf(px*px + py*py + pz*pz);
    float sg = 1.0f / (1.0f + expf(alpha*d - beta));
    float ssum = sg;
    #pragma unroll
    for (int s = 8; s >= 1; s >>= 1) ssum += __shfl_xor_sync(0xffffffffu, ssum, s);
    float dws = ssum + ((ssum == 0.0f) ? 1.0f : 0.0f) + 1e-6f;
    float dwk = sg / dws * (float)KNN;
    g_dw[(size_t)(b*M_ + m)*KNN + k] = dwk;

    px *= inr; py *= inr; pz *= inr;
    g_pts[(size_t)(b*M_ + m)*KNN + k] = make_float4(px, py, pz, 0.0f);

    float mom[9];
    mom[0]=px; mom[1]=py; mom[2]=pz;
    mom[3]=px*px; mom[4]=py*py; mom[5]=pz*pz;
    mom[6]=px*py; mom[7]=px*pz; mom[8]=py*pz;

    int lane = t & 31, wid = t >> 5;
    #pragma unroll
    for (int i = 0; i < 9; i++) {
        float v = mom[i];
        #pragma unroll
        for (int s = 16; s >= 1; s >>= 1) v += __shfl_xor_sync(0xffffffffu, v, s);
        if (lane == 0) s_red[wid*9 + i] = v;
    }
    __syncthreads();
    if (t < 9) {
        float a = 0.0f;
        #pragma unroll
        for (int w = 0; w < 8; w++) a += s_red[w*9 + t];
        g_part1[((size_t)b*NBLK1 + blockIdx.x)*16 + t] = a;
    }
    // ---- last-block finalize: analytic per-channel mean/var -> ab1 ----
    __syncthreads();
    __threadfence();
    __shared__ unsigned s_last;
    if (t == 0) s_last = (atomicAdd(&g_cnt1[b], 1u) == (unsigned)(NBLK1 - 1)) ? 1u : 0u;
    __syncthreads();
    if (s_last) {
        __shared__ float s_w[8];
        __shared__ float s_m[9];
        #pragma unroll 1
        for (int i = 0; i < 9; i++) {
            float r = g_part1[((size_t)b*NBLK1 + t)*16 + i]
                    + g_part1[((size_t)b*NBLK1 + t + 256)*16 + i];
            #pragma unroll
            for (int s = 16; s >= 1; s >>= 1) r += __shfl_xor_sync(0xffffffffu, r, s);
            if (lane == 0) s_w[wid] = r;
            __syncthreads();
            if (t == 0) {
                float a = 0.0f;
                #pragma unroll
                for (int w = 0; w < 8; w++) a += s_w[w];
                s_m[i] = a * MK_INV;
            }
            __syncthreads();
        }
        if (t < 16) {
            float w0 = fc1[t*3], w1 = fc1[t*3+1], w2 = fc1[t*3+2];
            float mean = w0*s_m[0] + w1*s_m[1] + w2*s_m[2];
            float ev2  = w0*w0*s_m[3] + w1*w1*s_m[4] + w2*w2*s_m[5]
                       + 2.0f*(w0*w1*s_m[6] + w0*w2*s_m[7] + w1*w2*s_m[8]);
            float var  = ev2 - mean*mean;
            float rstd = rsqrtf(var + 1e-5f);
            float sc = bnw[t] * rstd;
            g_ab1[b*16 + t] = make_float2(sc, bnb[t] - mean*sc);
        }
    }
}

// ---------------- pass 2: t1, mat1, mp1, t2 = fc2@[mat1;mp1]; last block -> ab2 -----
__global__ void k2(const float* __restrict__ fc1, const float* __restrict__ fc2,
                   const float* __restrict__ bnw, const float* __restrict__ bnb) {
    __shared__ float s_fc1[64];       // padded [ch][4]
    __shared__ float s_fc2[512];
    __shared__ float2 s_ab[16];
    __shared__ float s_red[8*32];
    int t = threadIdx.x, b = blockIdx.y;
    s_fc2[t] = fc2[t];
    s_fc2[t + 256] = fc2[t + 256];
    if (t < 16) {
        s_fc1[t*4+0] = fc1[t*3+0];
        s_fc1[t*4+1] = fc1[t*3+1];
        s_fc1[t*4+2] = fc1[t*3+2];
        s_fc1[t*4+3] = 0.0f;
        s_ab[t] = g_ab1[b*16 + t];
    }
    __syncthreads();

    int m = blockIdx.x * 16 + (t >> 4);
    int k = t & 15;
    int lane = t & 31, wid = t >> 5;
    float4 p = g_pts[(size_t)(b*M_ + m)*KNN + k];
    float dwk = g_dw[(size_t)(b*M_ + m)*KNN + k];

    float mat1[16], mp1[16];
    const float4* f1 = (const float4*)s_fc1;
    #pragma unroll
    for (int ch = 0; ch < 16; ch++) {
        float4 w = f1[ch];
        float v = w.x*p.x + w.y*p.y + w.z*p.z;
        float2 a = s_ab[ch];
        v = fmaxf(fmaf(v, a.x, a.y), 0.0f);
        mat1[ch] = v;
        float wmax = v * dwk;
        #pragma unroll
        for (int s = 8; s >= 1; s >>= 1) wmax = fmaxf(wmax, __shfl_xor_sync(0xffffffffu, wmax, s));
        mp1[ch] = wmax;
    }

    float t2v[16];
    const float4* f2 = (const float4*)s_fc2;
    #pragma unroll 4
    for (int j = 0; j < 16; j++) {
        float v = 0.0f;
        #pragma unroll
        for (int cq = 0; cq < 4; cq++) {
            float4 w = f2[j*8 + cq];
            v = fmaf(w.x, mat1[cq*4+0], v); v = fmaf(w.y, mat1[cq*4+1], v);
            v = fmaf(w.z, mat1[cq*4+2], v); v = fmaf(w.w, mat1[cq*4+3], v);
        }
        #pragma unroll
        for (int cq = 0; cq < 4; cq++) {
            float4 w = f2[j*8 + 4 + cq];
            v = fmaf(w.x, mp1[cq*4+0], v); v = fmaf(w.y, mp1[cq*4+1], v);
            v = fmaf(w.z, mp1[cq*4+2], v); v = fmaf(w.w, mp1[cq*4+3], v);
        }
        t2v[j] = v;
    }
    // store t2 layout [b][m][k][j]: 4 contiguous float4 per thread
    float4* o4 = (float4*)(g_t2 + (((size_t)(b*M_ + m)*16) + k)*16);
    o4[0] = make_float4(t2v[0], t2v[1], t2v[2], t2v[3]);
    o4[1] = make_float4(t2v[4], t2v[5], t2v[6], t2v[7]);
    o4[2] = make_float4(t2v[8], t2v[9], t2v[10], t2v[11]);
    o4[3] = make_float4(t2v[12], t2v[13], t2v[14], t2v[15]);

    // stats via partition-reduce: 31 shfl
    float stat[32];
    #pragma unroll
    for (int j = 0; j < 16; j++) { stat[j] = t2v[j]; stat[16+j] = t2v[j]*t2v[j]; }
    float r = preduce32(stat, lane);
    s_red[wid*32 + lane] = r;
    __syncthreads();
    if (t < 32) {
        float a = 0.0f;
        #pragma unroll
        for (int w = 0; w < 8; w++) a += s_red[w*32 + t];
        g_part2[((size_t)b*NBLK1 + blockIdx.x)*32 + t] = a;
    }
    // ---- last-block finalize -> ab2 ----
    __syncthreads();
    __threadfence();
    __shared__ unsigned s_last;
    if (t == 0) s_last = (atomicAdd(&g_cnt2[b], 1u) == (unsigned)(NBLK1 - 1)) ? 1u : 0u;
    __syncthreads();
    if (s_last) {
        __shared__ float s_p[8*32];
        __shared__ float s_c[32];
        float a0 = 0.0f, a1 = 0.0f, a2 = 0.0f, a3 = 0.0f;
        #pragma unroll 4
        for (int i = 0; i < 16; i++) {
            a0 += g_part2[((size_t)b*NBLK1 + wid*64 + i)*32 + lane];
            a1 += g_part2[((size_t)b*NBLK1 + wid*64 + 16 + i)*32 + lane];
            a2 += g_part2[((size_t)b*NBLK1 + wid*64 + 32 + i)*32 + lane];
            a3 += g_part2[((size_t)b*NBLK1 + wid*64 + 48 + i)*32 + lane];
        }
        s_p[wid*32 + lane] = (a0 + a1) + (a2 + a3);
        __syncthreads();
        if (t < 32) {
            float rr = 0.0f;
            #pragma unroll
            for (int w = 0; w < 8; w++) rr += s_p[w*32 + t];
            s_c[t] = rr;
        }
        __syncthreads();
        if (t < 16) {
            float mean = s_c[t] * MK_INV;
            float var  = s_c[t+16] * MK_INV - mean*mean;
            float rstd = rsqrtf(var + 1e-5f);
            float sc = bnw[t] * rstd;
            g_ab2[b*16 + t] = make_float2(sc, bnb[t] - mean*sc);
        }
    }
}

// ---------------- pass 3 (fused): mat3, gather+feat GEMM, cv GEMM ----------------
// 256 threads, 16 points per block, 2 CTAs/SM.
// Phase 3 uses o-pair f32x2 packing: 8o x 8p warp tile with 32-ull accumulator.
// smem floats: s_feat 16448 | s_mat3 4096 | s_fc3 512 | s_ab 32 | s_idx 256i
#define K4_SMEM ((16448 + 4096 + 512 + 32 + 256) * 4)

__global__ void __launch_bounds__(256, 2)
k4(const int* __restrict__ nbr, const float* __restrict__ fc3, float* __restrict__ out) {
    extern __shared__ __align__(16) float sm[];
    float* s_feat = sm;                          // 16448 floats (16 rows x 1028)
    float* s_mat3 = sm + 16448;                  // 4096 (also reused as s_fin)
    float* s_fc3  = sm + 16448 + 4096;           // 512
    float* s_ab   = sm + 16448 + 4096 + 512;     // 32
    int*   s_idx  = (int*)(sm + 16448 + 4096 + 512 + 32); // 256

    int t = threadIdx.x, b = blockIdx.y;
    int m0 = blockIdx.x * PTS_;

    s_fc3[t] = fc3[t];
    s_fc3[t + 256] = fc3[t + 256];
    s_idx[t] = nbr[((size_t)(b*M_) + m0)*KNN + t];
    if (t < 16) { float2 a = g_ab2[b*16 + t]; s_ab[t] = a.x; s_ab[16 + t] = a.y; }
    __syncthreads();

    // ---- phase 1: mat3[pt][k][j] ----
    {
        int pt = t >> 4, k = t & 15;
        int m = m0 + pt;
        float dwk = g_dw[(size_t)(b*M_ + m)*KNN + k];
        const float4* t24 = (const float4*)(g_t2 + (((size_t)(b*M_ + m)*16) + k)*16);
        float4 q0 = t24[0], q1 = t24[1], q2 = t24[2], q3 = t24[3];
        float mat2[16], mp2[16];
        mat2[0]=q0.x; mat2[1]=q0.y; mat2[2]=q0.z; mat2[3]=q0.w;
        mat2[4]=q1.x; mat2[5]=q1.y; mat2[6]=q1.z; mat2[7]=q1.w;
        mat2[8]=q2.x; mat2[9]=q2.y; mat2[10]=q2.z; mat2[11]=q2.w;
        mat2[12]=q3.x; mat2[13]=q3.y; mat2[14]=q3.z; mat2[15]=q3.w;
        #pragma unroll
        for (int ch = 0; ch < 16; ch++) {
            float v = fmaxf(fmaf(mat2[ch], s_ab[ch], s_ab[16 + ch]), 0.0f);
            mat2[ch] = v;
            float w = v * dwk;
            #pragma unroll
            for (int s = 8; s >= 1; s >>= 1) w = fmaxf(w, __shfl_xor_sync(0xffffffffu, w, s));
            mp2[ch] = w;
        }
        const float4* f3 = (const float4*)s_fc3;
        float t3[16];
        #pragma unroll 4
        for (int j = 0; j < 16; j++) {
            float v = 0.0f;
            #pragma unroll
            for (int cq = 0; cq < 4; cq++) {
                float4 w = f3[j*8 + cq];
                v = fmaf(w.x, mat2[cq*4+0], v); v = fmaf(w.y, mat2[cq*4+1], v);
                v = fmaf(w.z, mat2[cq*4+2], v); v = fmaf(w.w, mat2[cq*4+3], v);
            }
            #pragma unroll
            for (int cq = 0; cq < 4; cq++) {
                float4 w = f3[j*8 + 4 + cq];
                v = fmaf(w.x, mp2[cq*4+0], v); v = fmaf(w.y, mp2[cq*4+1], v);
                v = fmaf(w.z, mp2[cq*4+2], v); v = fmaf(w.w, mp2[cq*4+3], v);
            }
            t3[j] = fmaxf(v, 0.0f) * dwk;
        }
        float4* sm4 = (float4*)s_mat3;
        #pragma unroll
        for (int jg = 0; jg < 4; jg++)
            sm4[pt*64 + k*4 + jg] = make_float4(t3[jg*4], t3[jg*4+1], t3[jg*4+2], t3[jg*4+3]);
    }
    __syncthreads();

    // ---- phase 2: feat[pt][d = j*64 + c], packed f32x2 ----
    {
        int pt = t >> 4, cg = t & 15;           // 4 channels per thread
        ull facc2[4][8];
        #pragma unroll
        for (int i = 0; i < 4; i++)
            #pragma unroll
            for (int jp = 0; jp < 8; jp++) facc2[i][jp] = 0ull;

        const float4* xt4 = (const float4*)g_xt;
        const ulonglong2* sm2 = (const ulonglong2*)s_mat3;
        #pragma unroll 2
        for (int k = 0; k < 16; k++) {
            int n = s_idx[pt*16 + k];
            float4 xv = xt4[(size_t)(b*N_ + n)*16 + cg];
            ull d0 = dup2(xv.x), d1 = dup2(xv.y), d2 = dup2(xv.z), d3 = dup2(xv.w);
            #pragma unroll
            for (int q = 0; q < 4; q++) {
                ulonglong2 mv = sm2[pt*64 + k*4 + q];
                facc2[0][2*q]   = fma2(d0, mv.x, facc2[0][2*q]);
                facc2[1][2*q]   = fma2(d1, mv.x, facc2[1][2*q]);
                facc2[2][2*q]   = fma2(d2, mv.x, facc2[2][2*q]);
                facc2[3][2*q]   = fma2(d3, mv.x, facc2[3][2*q]);
                facc2[0][2*q+1] = fma2(d0, mv.y, facc2[0][2*q+1]);
                facc2[1][2*q+1] = fma2(d1, mv.y, facc2[1][2*q+1]);
                facc2[2][2*q+1] = fma2(d2, mv.y, facc2[2][2*q+1]);
                facc2[3][2*q+1] = fma2(d3, mv.y, facc2[3][2*q+1]);
            }
        }
        float4* sf4 = (float4*)s_feat;
        #pragma unroll
        for (int jp = 0; jp < 8; jp++) {
            float2 a0 = unpack2(facc2[0][jp]);
            float2 a1 = unpack2(facc2[1][jp]);
            float2 a2 = unpack2(facc2[2][jp]);
            float2 a3 = unpack2(facc2[3][jp]);
            sf4[pt*FS4 + (2*jp)  *16 + cg] = make_float4(a0.x, a1.x, a2.x, a3.x);
            sf4[pt*FS4 + (2*jp+1)*16 + cg] = make_float4(a0.y, a1.y, a2.y, a3.y);
        }
    }
    __syncthreads();

    // ---- phase 3: o-pair f32x2 GEMM. Warp tile 8o x 8p, acc[4 op][8 p]. ----
    // cvP2[op][d] pairs (cv[2op][d], cv[2op+1][d]); lane handles 2 d per step.
    {
        int warp = t >> 5, lane = t & 31;
        int wgrp = warp >> 1;                 // 0..3: op-group within pass
        int pbase = (warp & 1) * 8;           // 8 points per warp
        const float4* cv4 = (const float4*)g_cvP;
        const float* sf = s_feat;
        float* s_fin = s_mat3;                // reuse: [o][p] 64x16

        #pragma unroll 1
        for (int it = 0; it < 2; it++) {
            int opbase = (it*4 + wgrp)*4;     // 4 o-pairs = 8 o rows
            ull acc[4][8];
            #pragma unroll
            for (int oi = 0; oi < 4; oi++)
                #pragma unroll
                for (int pi = 0; pi < 8; pi++) acc[oi][pi] = 0ull;

            #pragma unroll 1
            for (int st = 0; st < 16; st++) {
                // wv[oi]: float4 = (o0,o1 @ d0 | o0,o1 @ d1), d0 = st*64 + 2*lane
                float4 w0f = cv4[(opbase + 0)*512 + st*32 + lane];
                float4 w1f = cv4[(opbase + 1)*512 + st*32 + lane];
                float4 w2f = cv4[(opbase + 2)*512 + st*32 + lane];
                float4 w3f = cv4[(opbase + 3)*512 + st*32 + lane];
                ulonglong2 w0 = *(ulonglong2*)&w0f;
                ulonglong2 w1 = *(ulonglong2*)&w1f;
                ulonglong2 w2 = *(ulonglong2*)&w2f;
                ulonglong2 w3 = *(ulonglong2*)&w3f;
                const float* fb = sf + st*64 + lane*2;
                #pragma unroll
                for (int pi = 0; pi < 8; pi++) {
                    float2 f = *(const float2*)(fb + (pbase + pi)*FSF);
                    ull b0 = dup2(f.x);
                    ull b1 = dup2(f.y);
                    acc[0][pi] = fma2(w0.x, b0, acc[0][pi]);
                    acc[0][pi] = fma2(w0.y, b1, acc[0][pi]);
                    acc[1][pi] = fma2(w1.x, b0, acc[1][pi]);
                    acc[1][pi] = fma2(w1.y, b1, acc[1][pi]);
                    acc[2][pi] = fma2(w2.x, b0, acc[2][pi]);
                    acc[2][pi] = fma2(w2.y, b1, acc[2][pi]);
                    acc[3][pi] = fma2(w3.x, b0, acc[3][pi]);
                    acc[3][pi] = fma2(w3.y, b1, acc[3][pi]);
                }
            }
            // acc[oi][pi] = (out[2*(opbase+oi)], out[2*(opbase+oi)+1]) partials.
            // Partition-reduce even/odd halves (2 x 31 shfl).
            float ve[32], vo[32];
            #pragma unroll
            for (int oi = 0; oi < 4; oi++)
                #pragma unroll
                for (int pi = 0; pi < 8; pi++) {
                    float2 h = unpack2(acc[oi][pi]);
                    ve[oi*8 + pi] = h.x;
                    vo[oi*8 + pi] = h.y;
                }
            float re = preduce32(ve, lane);
            float ro = preduce32(vo, lane);
            int oe = 2*(opbase + (lane >> 3));
            int pp = pbase + (lane & 7);
            s_fin[oe*16 + pp]       = re;
            s_fin[(oe + 1)*16 + pp] = ro;
        }
    }
    __syncthreads();

    // coalesced output write: 64 o x 16 p = 1024 floats, 256 threads x float4
    {
        int o = t >> 2, pq = t & 3;
        float4 v = ((const float4*)s_mat3)[o*4 + pq];
        ((float4*)out)[((size_t)(b*64 + o))*2048 + (m0 >> 2) + pq] = v;
    }
}

// ---------------- launch ----------------
extern "C" void kernel_launch(void* const* d_in, const int* in_sizes, int n_in,
                              void* d_out, int out_size) {
    const float* x     = (const float*)d_in[0];
    const float* pos   = (const float*)d_in[1];
    const float* sup   = (const float*)d_in[2];
    const int*   nbr   = (const int*)  d_in[3];
    const float* alpha = (const float*)d_in[4];
    const float* beta  = (const float*)d_in[5];
    const float* nr    = (const float*)d_in[6];
    const float* fc1   = (const float*)d_in[7];
    const float* fc2   = (const float*)d_in[8];
    const float* fc3   = (const float*)d_in[9];
    const float* bn1w  = (const float*)d_in[10];
    const float* bn1b  = (const float*)d_in[11];
    const float* bn2w  = (const float*)d_in[12];
    const float* bn2b  = (const float*)d_in[13];
    const float* cvw   = (const float*)d_in[14];
    float* out = (float*)d_out;

    cudaFuncSetAttribute((const void*)k4, cudaFuncAttributeMaxDynamicSharedMemorySize, K4_SMEM);

    k_prep<<<2432, 256>>>(x, pos, cvw);
    k1    <<<dim3(NBLK1, B_), 256>>>(sup, nbr, alpha, beta, nr, fc1, bn1w, bn1b);
    k2    <<<dim3(NBLK1, B_), 256>>>(fc1, fc2, bn2w, bn2b);
    k4    <<<dim3(M_/PTS_, B_), 256, K4_SMEM>>>(nbr, fc3, out);
}